// round 9
// baseline (speedup 1.0000x reference)
#include <cuda_runtime.h>
#include <cuda_fp16.h>
#include <cstdint>
#include <math.h>

// dims: B=64, T=1024, ANNOT=512, RNN=1024, MEM=512, ATTN=512, FILTERS=32, KSIZE=31
// outputs: rnn_output[64,1024] | new_context[64,512] | alignment[64,1024] (float32)

__device__ float g_gpart[2 * 8 * 64 * 3072];   // [sel][kpart][b][j]
__device__ float g_pqpart[32 * 64 * 512];      // [kp][b][a]
__device__ float g_pq[64 * 512];
__device__ float g_part[8 * 64 * 1024];        // [atile*2+wn][b][t]

__device__ __half g_annots_h[64 * 1024 * 512]; // [b][t][d]  (64 MB)
__device__ __half g_awh[512 * 512];            // [a][d]
__device__ __half g_locwh[512 * 32];           // [a][f]
__device__ __half g_lconvh[64 * 1024 * 32];    // [b][t][f]

__device__ __forceinline__ float sigmoidf_(float x) { return 1.f / (1.f + expf(-x)); }

__device__ __forceinline__ float tanh_fast(float x) {
    float y;
    asm("tanh.approx.f32 %0, %1;" : "=f"(y) : "f"(x));
    return y;
}

__device__ __forceinline__ void mma_f16(float* d, const unsigned* a,
                                        unsigned b0, unsigned b1) {
    asm volatile(
        "mma.sync.aligned.m16n8k16.row.col.f32.f16.f16.f32 "
        "{%0,%1,%2,%3}, {%4,%5,%6,%7}, {%8,%9}, {%0,%1,%2,%3};"
        : "+f"(d[0]), "+f"(d[1]), "+f"(d[2]), "+f"(d[3])
        : "r"(a[0]), "r"(a[1]), "r"(a[2]), "r"(a[3]), "r"(b0), "r"(b1));
}

__device__ __forceinline__ void cp_async16(void* smem_dst, const void* gmem_src) {
    uint32_t s;
    asm("{ .reg .u64 t; cvta.to.shared.u64 t, %1; cvt.u32.u64 %0, t; }"
        : "=r"(s) : "l"(smem_dst));
    asm volatile("cp.async.ca.shared.global [%0], [%1], 16;" :: "r"(s), "l"(gmem_src));
}
__device__ __forceinline__ void cp_commit() {
    asm volatile("cp.async.commit_group;");
}
template <int N>
__device__ __forceinline__ void cp_wait() {
    asm volatile("cp.async.wait_group %0;" :: "n"(N));
}

__device__ __forceinline__ unsigned pack_h2(float a, float b) {
    __half2 h = __floats2half2_rn(a, b);
    return *reinterpret_cast<unsigned*>(&h);
}

// ---------------------------------------------------------------------------
// fp32 -> fp16 conversion passes
// ---------------------------------------------------------------------------
__global__ __launch_bounds__(256) void k_cvt_annots(const float* __restrict__ src)
{
    size_t i = ((size_t)blockIdx.x * 256 + threadIdx.x) * 8;   // 33.5M elements
    float4 x = *(const float4*)(src + i);
    float4 y = *(const float4*)(src + i + 4);
    uint4 o;
    o.x = pack_h2(x.x, x.y); o.y = pack_h2(x.z, x.w);
    o.z = pack_h2(y.x, y.y); o.w = pack_h2(y.z, y.w);
    *reinterpret_cast<uint4*>(&g_annots_h[i]) = o;
}

__global__ __launch_bounds__(256) void k_cvt_w(const float* __restrict__ a_w,
                                               const float* __restrict__ loc_w)
{
    int bx = blockIdx.x;
    const float* src; __half* dst; size_t base;
    if (bx < 128) { src = a_w;  dst = g_awh;   base = (size_t)bx * 2048; }
    else          { src = loc_w; dst = g_locwh; base = (size_t)(bx - 128) * 2048; }
    size_t i = base + threadIdx.x * 8;
    float4 x = *(const float4*)(src + i);
    float4 y = *(const float4*)(src + i + 4);
    uint4 o;
    o.x = pack_h2(x.x, x.y); o.y = pack_h2(x.z, x.w);
    o.z = pack_h2(y.x, y.y); o.w = pack_h2(y.z, y.w);
    *reinterpret_cast<uint4*>(&dst[i]) = o;
}

// ---------------------------------------------------------------------------
// GRU GEMMs, batch-tiled split-K (K=1024 both). grid (24, 8, 2), block 256.
// ---------------------------------------------------------------------------
__global__ __launch_bounds__(256) void k_gru_gemm(
    const float* __restrict__ mem, const float* __restrict__ ctx,
    const float* __restrict__ hst,
    const float* __restrict__ W_ih, const float* __restrict__ W_hh)
{
    __shared__ float Xs[64 * 36];
    __shared__ float Ws[32 * 132];

    int tid = threadIdx.x;
    int nt = blockIdx.x * 128;
    int kp = blockIdx.y;
    int sel = blockIdx.z;
    const int K = 1024;
    const int klen = 128;
    int kbeg = kp * klen;
    const float* W = sel ? W_hh : W_ih;

    int ty = tid >> 4, tx = tid & 15;
    int r0 = tid >> 3, c8 = tid & 7;

    float acc[4][8];
#pragma unroll
    for (int i = 0; i < 4; ++i)
#pragma unroll
        for (int j = 0; j < 8; ++j) acc[i][j] = 0.f;

    for (int kb = kbeg; kb < kbeg + klen; kb += 32) {
        __syncthreads();
#pragma unroll
        for (int p = 0; p < 2; ++p) {
            int row = r0 + p * 32;
            int k = kb + c8 * 4;
            const float* src;
            if (sel) src = hst + row * 1024 + k;
            else src = (k < 512) ? mem + row * 512 + k
                                 : ctx + row * 512 + (k - 512);
            *(float4*)&Xs[row * 36 + c8 * 4] = *(const float4*)src;
        }
#pragma unroll
        for (int p = 0; p < 4; ++p) {
            int j = r0 + p * 32;
            float4 w = *(const float4*)&W[(size_t)(nt + j) * K + kb + c8 * 4];
            Ws[(c8 * 4 + 0) * 132 + j] = w.x;
            Ws[(c8 * 4 + 1) * 132 + j] = w.y;
            Ws[(c8 * 4 + 2) * 132 + j] = w.z;
            Ws[(c8 * 4 + 3) * 132 + j] = w.w;
        }
        __syncthreads();
#pragma unroll
        for (int k = 0; k < 32; ++k) {
            float4 w0 = *(const float4*)&Ws[k * 132 + tx * 8];
            float4 w1 = *(const float4*)&Ws[k * 132 + tx * 8 + 4];
#pragma unroll
            for (int i = 0; i < 4; ++i) {
                float x = Xs[(ty * 4 + i) * 36 + k];
                acc[i][0] += x * w0.x; acc[i][1] += x * w0.y;
                acc[i][2] += x * w0.z; acc[i][3] += x * w0.w;
                acc[i][4] += x * w1.x; acc[i][5] += x * w1.y;
                acc[i][6] += x * w1.z; acc[i][7] += x * w1.w;
            }
        }
    }
#pragma unroll
    for (int i = 0; i < 4; ++i) {
        float* dst = g_gpart + ((size_t)(sel * 8 + kp) * 64 + ty * 4 + i) * 3072
                   + nt + tx * 8;
#pragma unroll
        for (int j = 0; j < 8; ++j) dst[j] = acc[i][j];
    }
}

// ---------------------------------------------------------------------------
// GRU gating
// ---------------------------------------------------------------------------
__global__ void k_gru_gate(const float* __restrict__ hst,
                           const float* __restrict__ b_ih,
                           const float* __restrict__ b_hh,
                           float* __restrict__ out)
{
    int idx = blockIdx.x * 256 + threadIdx.x;
    int b = idx >> 10, j = idx & 1023;
    float gi_r = 0.f, gi_z = 0.f, gi_n = 0.f;
    float gh_r = 0.f, gh_z = 0.f, gh_n = 0.f;
#pragma unroll
    for (int kp = 0; kp < 8; ++kp) {
        const float* pi = g_gpart + ((size_t)kp * 64 + b) * 3072;
        const float* ph = g_gpart + ((size_t)(8 + kp) * 64 + b) * 3072;
        gi_r += pi[j]; gi_z += pi[j + 1024]; gi_n += pi[j + 2048];
        gh_r += ph[j]; gh_z += ph[j + 1024]; gh_n += ph[j + 2048];
    }
    gi_r += b_ih[j]; gi_z += b_ih[j + 1024]; gi_n += b_ih[j + 2048];
    gh_r += b_hh[j]; gh_z += b_hh[j + 1024]; gh_n += b_hh[j + 2048];
    float r = sigmoidf_(gi_r + gh_r);
    float z = sigmoidf_(gi_z + gh_z);
    float n = tanhf(gi_n + r * gh_n);
    out[idx] = (1.f - z) * n + z * hst[idx];
}

// ---------------------------------------------------------------------------
// processed_query, split-K=32 batch-tiled: partial[kp][b][a]
// grid (4 ntiles of 128, 32 kp), block 256
// ---------------------------------------------------------------------------
__global__ __launch_bounds__(256) void k_pq_g(
    const float* __restrict__ rnn, const float* __restrict__ q_w)
{
    __shared__ float Xs[64 * 36];
    __shared__ float Ws[32 * 132];

    int tid = threadIdx.x;
    int nt = blockIdx.x * 128;
    int kb = blockIdx.y * 32;

    int ty = tid >> 4, tx = tid & 15;
    int r0 = tid >> 3, c8 = tid & 7;

    float acc[4][8];
#pragma unroll
    for (int i = 0; i < 4; ++i)
#pragma unroll
        for (int j = 0; j < 8; ++j) acc[i][j] = 0.f;

#pragma unroll
    for (int p = 0; p < 2; ++p) {
        int row = r0 + p * 32;
        *(float4*)&Xs[row * 36 + c8 * 4] = *(const float4*)(rnn + row * 1024 + kb + c8 * 4);
    }
#pragma unroll
    for (int p = 0; p < 4; ++p) {
        int j = r0 + p * 32;
        float4 w = *(const float4*)&q_w[(size_t)(nt + j) * 1024 + kb + c8 * 4];
        Ws[(c8 * 4 + 0) * 132 + j] = w.x;
        Ws[(c8 * 4 + 1) * 132 + j] = w.y;
        Ws[(c8 * 4 + 2) * 132 + j] = w.z;
        Ws[(c8 * 4 + 3) * 132 + j] = w.w;
    }
    __syncthreads();
#pragma unroll
    for (int k = 0; k < 32; ++k) {
        float4 w0 = *(const float4*)&Ws[k * 132 + tx * 8];
        float4 w1 = *(const float4*)&Ws[k * 132 + tx * 8 + 4];
#pragma unroll
        for (int i = 0; i < 4; ++i) {
            float x = Xs[(ty * 4 + i) * 36 + k];
            acc[i][0] += x * w0.x; acc[i][1] += x * w0.y;
            acc[i][2] += x * w0.z; acc[i][3] += x * w0.w;
            acc[i][4] += x * w1.x; acc[i][5] += x * w1.y;
            acc[i][6] += x * w1.z; acc[i][7] += x * w1.w;
        }
    }
#pragma unroll
    for (int i = 0; i < 4; ++i) {
        float* dst = g_pqpart + ((size_t)blockIdx.y * 64 + ty * 4 + i) * 512
                   + nt + tx * 8;
#pragma unroll
        for (int j = 0; j < 8; ++j) dst[j] = acc[i][j];
    }
}

__global__ void k_pq_comb(const float* __restrict__ q_b)
{
    int idx = blockIdx.x * 256 + threadIdx.x;  // 32768
    int a = idx & 511;
    float s = q_b[a];
#pragma unroll
    for (int kp = 0; kp < 32; ++kp) s += g_pqpart[kp * 32768 + idx];
    g_pq[idx] = s;
}

// ---------------------------------------------------------------------------
// location conv -> g_lconvh[b][t][f] (half)
// ---------------------------------------------------------------------------
__global__ __launch_bounds__(256) void k_conv(
    const float* __restrict__ atten, const float* __restrict__ conv_w)
{
    __shared__ float sA[2 * 1056];
    __shared__ float sW[16 * 62];
    int b = blockIdx.x, fg = blockIdx.y;
    int tid = threadIdx.x;
    for (int i = tid; i < 2 * 1056; i += 256) {
        int c = i / 1056;
        int p = i % 1056;
        int t = p - 15;
        float v = 0.f;
        if (t >= 0 && t < 1024) v = atten[b * 2048 + c * 1024 + t];
        sA[i] = v;
    }
    for (int i = tid; i < 16 * 62; i += 256) {
        int fo = i / 62, r = i % 62;
        sW[i] = conv_w[(fg * 16 + fo) * 62 + r];
    }
    __syncthreads();
#pragma unroll
    for (int p = 0; p < 4; ++p) {
        int t = tid + p * 256;
        float acc[16];
#pragma unroll
        for (int f = 0; f < 16; ++f) acc[f] = 0.f;
#pragma unroll
        for (int c = 0; c < 2; ++c)
#pragma unroll
            for (int k = 0; k < 31; ++k) {
                float a = sA[c * 1056 + t + k];
#pragma unroll
                for (int f = 0; f < 16; ++f) acc[f] += a * sW[f * 62 + c * 31 + k];
            }
        __half* dst = g_lconvh + (size_t)b * 32768 + t * 32 + fg * 16;
        uint4 o0, o1;
        o0.x = pack_h2(acc[0], acc[1]);   o0.y = pack_h2(acc[2], acc[3]);
        o0.z = pack_h2(acc[4], acc[5]);   o0.w = pack_h2(acc[6], acc[7]);
        o1.x = pack_h2(acc[8], acc[9]);   o1.y = pack_h2(acc[10], acc[11]);
        o1.z = pack_h2(acc[12], acc[13]); o1.w = pack_h2(acc[14], acc[15]);
        *reinterpret_cast<uint4*>(dst) = o0;
        *reinterpret_cast<uint4*>(dst + 8) = o1;
    }
}

// ---------------------------------------------------------------------------
// Energy GEMM, f16 mma.sync m16n8k16 + cp.async double-buffered pipeline.
// Block tile 128t x 128a, 8 warps (4x2). K = 8 chunks of 64 (annot) + 1 of 32 (conv).
// grid (4, 512), block 256, dynamic smem.
// ---------------------------------------------------------------------------
#define EPADH 72                       // halves per smem row (144B, conflict-free)
#define ETILEH (128 * EPADH)           // halves per tile
#define E_SMEM_BYTES (4 * ETILEH * 2 + 1024)

__global__ __launch_bounds__(256) void k_energy(
    const float* __restrict__ a_b, const float* __restrict__ loc_b,
    const float* __restrict__ v_w)
{
    extern __shared__ char smem[];
    __half* Ah[2] = { (__half*)smem,                    (__half*)(smem + 2 * ETILEH * 2) };
    __half* Bh[2] = { (__half*)(smem + ETILEH * 2),     (__half*)(smem + 3 * ETILEH * 2) };
    float* c_s = (float*)(smem + 4 * ETILEH * 2);
    float* v_s = c_s + 128;

    int tid = threadIdx.x;
    int warp = tid >> 5, lane = tid & 31;
    int wm = warp >> 1, wn = warp & 1;
    int g = lane >> 2, tg = lane & 3;

    int atile = blockIdx.x;
    int mtile = blockIdx.y;
    int b = mtile >> 3;
    int t0 = (mtile & 7) << 7;
    int abase = atile << 7;

    if (tid < 128) {
        int a = abase + tid;
        c_s[tid] = g_pq[b * 512 + a] + a_b[a] + loc_b[a];
        v_s[tid] = v_w[a];
    }

    const __half* baseA = g_annots_h + ((size_t)(b * 1024 + t0)) * 512;
    const __half* baseB = g_awh + (size_t)abase * 512;
    const __half* convA = g_lconvh + (size_t)b * 32768 + (size_t)t0 * 32;
    const __half* convB = g_locwh + (size_t)abase * 32;

    auto issue = [&](int kc, int bf) {
        if (kc < 8) {
            const __half* gA = baseA + kc * 64;
            const __half* gB = baseB + kc * 64;
#pragma unroll
            for (int p = 0; p < 4; ++p) {
                int lin = tid + p * 256;
                int row = lin >> 3, seg = lin & 7;
                cp_async16(&Ah[bf][row * EPADH + seg * 8], gA + (size_t)row * 512 + seg * 8);
            }
#pragma unroll
            for (int p = 0; p < 4; ++p) {
                int lin = tid + p * 256;
                int row = lin >> 3, seg = lin & 7;
                cp_async16(&Bh[bf][row * EPADH + seg * 8], gB + (size_t)row * 512 + seg * 8);
            }
        } else {
#pragma unroll
            for (int p = 0; p < 2; ++p) {
                int lin = tid + p * 256;
                int row = lin >> 2, seg = lin & 3;
                cp_async16(&Ah[bf][row * EPADH + seg * 8], convA + (size_t)row * 32 + seg * 8);
            }
#pragma unroll
            for (int p = 0; p < 2; ++p) {
                int lin = tid + p * 256;
                int row = lin >> 2, seg = lin & 3;
                cp_async16(&Bh[bf][row * EPADH + seg * 8], convB + (size_t)row * 32 + seg * 8);
            }
        }
        cp_commit();
    };

    float acc[2][8][4];
#pragma unroll
    for (int mf = 0; mf < 2; ++mf)
#pragma unroll
        for (int nf = 0; nf < 8; ++nf)
#pragma unroll
            for (int q = 0; q < 4; ++q) acc[mf][nf][q] = 0.f;

    issue(0, 0);

    for (int kc = 0; kc < 9; ++kc) {
        int bf = kc & 1;
        if (kc + 1 < 9) {
            issue(kc + 1, bf ^ 1);
            cp_wait<1>();
        } else {
            cp_wait<0>();
        }
        __syncthreads();

        const __half* AA = Ah[bf];
        const __half* BB = Bh[bf];
        int nks = (kc < 8) ? 4 : 2;
#pragma unroll
        for (int ks = 0; ks < 4; ++ks) {
            if (ks >= nks) break;
            int k0 = ks * 16;
            unsigned a_frag[2][4];
#pragma unroll
            for (int mf = 0; mf < 2; ++mf) {
                int rb = wm * 32 + mf * 16;
                a_frag[mf][0] = *(const unsigned*)(AA + (rb + g) * EPADH + k0 + 2 * tg);
                a_frag[mf][1] = *(const unsigned*)(AA + (rb + g + 8) * EPADH + k0 + 2 * tg);
                a_frag[mf][2] = *(const unsigned*)(AA + (rb + g) * EPADH + k0 + 8 + 2 * tg);
                a_frag[mf][3] = *(const unsigned*)(AA + (rb + g + 8) * EPADH + k0 + 8 + 2 * tg);
            }
#pragma unroll
            for (int nf = 0; nf < 8; ++nf) {
                int ar = wn * 64 + nf * 8 + g;
                unsigned b0 = *(const unsigned*)(BB + ar * EPADH + k0 + 2 * tg);
                unsigned b1 = *(const unsigned*)(BB + ar * EPADH + k0 + 8 + 2 * tg);
                mma_f16(acc[0][nf], a_frag[0], b0, b1);
                mma_f16(acc[1][nf], a_frag[1], b0, b1);
            }
        }
        __syncthreads();
    }

    // epilogue: bias + tanh + v-weight, reduce over a within warp
#pragma unroll
    for (int mf = 0; mf < 2; ++mf) {
#pragma unroll
        for (int rh = 0; rh < 2; ++rh) {
            float s = 0.f;
#pragma unroll
            for (int nf = 0; nf < 8; ++nf) {
                int a0 = wn * 64 + nf * 8 + 2 * tg;
                float x = acc[mf][nf][rh * 2 + 0] + c_s[a0];
                float y = acc[mf][nf][rh * 2 + 1] + c_s[a0 + 1];
                s += v_s[a0] * tanh_fast(x) + v_s[a0 + 1] * tanh_fast(y);
            }
            s += __shfl_xor_sync(0xffffffffu, s, 1);
            s += __shfl_xor_sync(0xffffffffu, s, 2);
            if (tg == 0) {
                int t = t0 + wm * 32 + mf * 16 + rh * 8 + g;
                g_part[((size_t)(atile * 2 + wn) * 64 + b) * 1024 + t] = s;
            }
        }
    }
}

// ---------------------------------------------------------------------------
// mask + sigmoid + row normalize -> alignment
// ---------------------------------------------------------------------------
__global__ void k_norm(const int* __restrict__ mask, float* __restrict__ out)
{
    int b = blockIdx.x, tid = threadIdx.x;
    __shared__ float red[256];
    float s[4];
    float loc = 0.f;
#pragma unroll
    for (int i = 0; i < 4; ++i) {
        int t = tid + i * 256;
        float raw = 0.f;
#pragma unroll
        for (int sl = 0; sl < 8; ++sl) raw += g_part[sl * 65536 + b * 1024 + t];
        float v = (mask[b * 1024 + t] != 0) ? 1.f / (1.f + expf(-raw)) : 0.f;
        s[i] = v;
        loc += v;
    }
    red[tid] = loc;
    __syncthreads();
    for (int st = 128; st; st >>= 1) {
        if (tid < st) red[tid] += red[tid + st];
        __syncthreads();
    }
    float inv = 1.f / red[0];
#pragma unroll
    for (int i = 0; i < 4; ++i)
        out[98304 + b * 1024 + tid + i * 256] = s[i] * inv;
}

// ---------------------------------------------------------------------------
// new_context[b,d] = sum_t align[b,t] * annots[b,t,d]
// ---------------------------------------------------------------------------
__global__ __launch_bounds__(512) void k_ctx(
    const float* __restrict__ annots, const float* __restrict__ align,
    float* __restrict__ outc)
{
    __shared__ float w[1024];
    __shared__ float red[512];
    int b = blockIdx.y, d0 = blockIdx.x * 128;
    int tid = threadIdx.x;
    for (int i = tid; i < 1024; i += 512) w[i] = align[b * 1024 + i];
    __syncthreads();
    int d = d0 + (tid & 127);
    int part = tid >> 7;
    const float* A = annots + (size_t)(b * 1024 + part * 256) * 512 + d;
    float acc = 0.f;
#pragma unroll 8
    for (int t = 0; t < 256; ++t) acc += w[part * 256 + t] * A[(size_t)t * 512];
    red[tid] = acc;
    __syncthreads();
    if (part == 0)
        outc[b * 512 + d] = red[tid] + red[tid + 128] + red[tid + 256] + red[tid + 384];
}

// ---------------------------------------------------------------------------
extern "C" void kernel_launch(void* const* d_in, const int* in_sizes, int n_in,
                              void* d_out, int out_size)
{
    const float* memory    = (const float*)d_in[0];
    const float* context   = (const float*)d_in[1];
    const float* rnn_state = (const float*)d_in[2];
    const float* annots    = (const float*)d_in[3];
    const float* atten     = (const float*)d_in[4];
    const int*   mask      = (const int*)d_in[5];

    int w = 6;
    if (n_in >= 19 && in_sizes[6] == 1) w = 7;

    const float* W_ih   = (const float*)d_in[w + 0];
    const float* W_hh   = (const float*)d_in[w + 1];
    const float* b_ih   = (const float*)d_in[w + 2];
    const float* b_hh   = (const float*)d_in[w + 3];
    const float* conv_w = (const float*)d_in[w + 4];
    const float* loc_w  = (const float*)d_in[w + 5];
    const float* loc_b  = (const float*)d_in[w + 6];
    const float* q_w    = (const float*)d_in[w + 7];
    const float* q_b    = (const float*)d_in[w + 8];
    const float* a_w    = (const float*)d_in[w + 9];
    const float* a_b    = (const float*)d_in[w + 10];
    const float* v_w    = (const float*)d_in[w + 11];

    float* out = (float*)d_out;
    // layout: [rnn_output 64*1024][new_context 64*512][alignment 64*1024]

    static int smem_set = 0;
    if (!smem_set) {
        cudaFuncSetAttribute(k_energy, cudaFuncAttributeMaxDynamicSharedMemorySize,
                             E_SMEM_BYTES);
        smem_set = 1;
    }

    k_cvt_annots<<<16384, 256>>>(annots);
    k_cvt_w<<<136, 256>>>(a_w, loc_w);
    k_gru_gemm<<<dim3(24, 8, 2), 256>>>(memory, context, rnn_state, W_ih, W_hh);
    k_conv<<<dim3(64, 2), 256>>>(atten, conv_w);
    k_gru_gate<<<256, 256>>>(rnn_state, b_ih, b_hh, out);
    k_pq_g<<<dim3(4, 32), 256>>>(out, q_w);
    k_pq_comb<<<128, 256>>>(q_b);
    k_energy<<<dim3(4, 512), 256, E_SMEM_BYTES>>>(a_b, loc_b, v_w);
    k_norm<<<64, 256>>>(mask, out);
    k_ctx<<<dim3(4, 64), 512>>>(annots, out + 98304, out + 65536);
}

// round 10
// speedup vs baseline: 1.0053x; 1.0053x over previous
#include <cuda_runtime.h>
#include <cuda_fp16.h>
#include <cstdint>
#include <math.h>

// dims: B=64, T=1024, ANNOT=512, RNN=1024, MEM=512, ATTN=512, FILTERS=32, KSIZE=31
// outputs: rnn_output[64,1024] | new_context[64,512] | alignment[64,1024] (float32)

__device__ float g_gpart[2 * 8 * 64 * 3072];   // [sel][kpart][b][j]
__device__ float g_pqpart[32 * 64 * 512];      // [kp][b][a]
__device__ float g_pq[64 * 512];
__device__ float g_part[8 * 64 * 1024];        // [atile*2+wn][b][t]

__device__ __half g_annots_h[64 * 1024 * 512]; // [b][t][d]  (64 MB)
__device__ __half g_awh[512 * 512];            // [a][d]
__device__ __half g_locwh[512 * 32];           // [a][f]
__device__ __half g_lconvh[64 * 1024 * 32];    // [b][t][f]

__device__ __forceinline__ float sigmoidf_(float x) { return 1.f / (1.f + expf(-x)); }

__device__ __forceinline__ float tanh_fast(float x) {
    float y;
    asm("tanh.approx.f32 %0, %1;" : "=f"(y) : "f"(x));
    return y;
}

__device__ __forceinline__ void mma_f16(float* d, const unsigned* a,
                                        unsigned b0, unsigned b1) {
    asm volatile(
        "mma.sync.aligned.m16n8k16.row.col.f32.f16.f16.f32 "
        "{%0,%1,%2,%3}, {%4,%5,%6,%7}, {%8,%9}, {%0,%1,%2,%3};"
        : "+f"(d[0]), "+f"(d[1]), "+f"(d[2]), "+f"(d[3])
        : "r"(a[0]), "r"(a[1]), "r"(a[2]), "r"(a[3]), "r"(b0), "r"(b1));
}

__device__ __forceinline__ void cp_async16(void* smem_dst, const void* gmem_src) {
    uint32_t s;
    asm("{ .reg .u64 t; cvta.to.shared.u64 t, %1; cvt.u32.u64 %0, t; }"
        : "=r"(s) : "l"(smem_dst));
    asm volatile("cp.async.ca.shared.global [%0], [%1], 16;" :: "r"(s), "l"(gmem_src));
}
__device__ __forceinline__ void cp_commit() {
    asm volatile("cp.async.commit_group;");
}
template <int N>
__device__ __forceinline__ void cp_wait() {
    asm volatile("cp.async.wait_group %0;" :: "n"(N));
}

__device__ __forceinline__ unsigned pack_h2(float a, float b) {
    __half2 h = __floats2half2_rn(a, b);
    return *reinterpret_cast<unsigned*>(&h);
}

// ---------------------------------------------------------------------------
// fp32 -> fp16 conversion passes
// ---------------------------------------------------------------------------
__global__ __launch_bounds__(256) void k_cvt_annots(const float* __restrict__ src)
{
    size_t i = ((size_t)blockIdx.x * 256 + threadIdx.x) * 8;   // 33.5M elements
    float4 x = *(const float4*)(src + i);
    float4 y = *(const float4*)(src + i + 4);
    uint4 o;
    o.x = pack_h2(x.x, x.y); o.y = pack_h2(x.z, x.w);
    o.z = pack_h2(y.x, y.y); o.w = pack_h2(y.z, y.w);
    *reinterpret_cast<uint4*>(&g_annots_h[i]) = o;
}

__global__ __launch_bounds__(256) void k_cvt_w(const float* __restrict__ a_w,
                                               const float* __restrict__ loc_w)
{
    int bx = blockIdx.x;
    const float* src; __half* dst; size_t base;
    if (bx < 128) { src = a_w;  dst = g_awh;   base = (size_t)bx * 2048; }
    else          { src = loc_w; dst = g_locwh; base = (size_t)(bx - 128) * 2048; }
    size_t i = base + threadIdx.x * 8;
    float4 x = *(const float4*)(src + i);
    float4 y = *(const float4*)(src + i + 4);
    uint4 o;
    o.x = pack_h2(x.x, x.y); o.y = pack_h2(x.z, x.w);
    o.z = pack_h2(y.x, y.y); o.w = pack_h2(y.z, y.w);
    *reinterpret_cast<uint4*>(&dst[i]) = o;
}

// ---------------------------------------------------------------------------
// GRU GEMMs, batch-tiled split-K (K=1024 both). grid (24, 8, 2), block 256.
// ---------------------------------------------------------------------------
__global__ __launch_bounds__(256) void k_gru_gemm(
    const float* __restrict__ mem, const float* __restrict__ ctx,
    const float* __restrict__ hst,
    const float* __restrict__ W_ih, const float* __restrict__ W_hh)
{
    __shared__ float Xs[64 * 36];
    __shared__ float Ws[32 * 132];

    int tid = threadIdx.x;
    int nt = blockIdx.x * 128;
    int kp = blockIdx.y;
    int sel = blockIdx.z;
    const int K = 1024;
    const int klen = 128;
    int kbeg = kp * klen;
    const float* W = sel ? W_hh : W_ih;

    int ty = tid >> 4, tx = tid & 15;
    int r0 = tid >> 3, c8 = tid & 7;

    float acc[4][8];
#pragma unroll
    for (int i = 0; i < 4; ++i)
#pragma unroll
        for (int j = 0; j < 8; ++j) acc[i][j] = 0.f;

    for (int kb = kbeg; kb < kbeg + klen; kb += 32) {
        __syncthreads();
#pragma unroll
        for (int p = 0; p < 2; ++p) {
            int row = r0 + p * 32;
            int k = kb + c8 * 4;
            const float* src;
            if (sel) src = hst + row * 1024 + k;
            else src = (k < 512) ? mem + row * 512 + k
                                 : ctx + row * 512 + (k - 512);
            *(float4*)&Xs[row * 36 + c8 * 4] = *(const float4*)src;
        }
#pragma unroll
        for (int p = 0; p < 4; ++p) {
            int j = r0 + p * 32;
            float4 w = *(const float4*)&W[(size_t)(nt + j) * K + kb + c8 * 4];
            Ws[(c8 * 4 + 0) * 132 + j] = w.x;
            Ws[(c8 * 4 + 1) * 132 + j] = w.y;
            Ws[(c8 * 4 + 2) * 132 + j] = w.z;
            Ws[(c8 * 4 + 3) * 132 + j] = w.w;
        }
        __syncthreads();
#pragma unroll
        for (int k = 0; k < 32; ++k) {
            float4 w0 = *(const float4*)&Ws[k * 132 + tx * 8];
            float4 w1 = *(const float4*)&Ws[k * 132 + tx * 8 + 4];
#pragma unroll
            for (int i = 0; i < 4; ++i) {
                float x = Xs[(ty * 4 + i) * 36 + k];
                acc[i][0] += x * w0.x; acc[i][1] += x * w0.y;
                acc[i][2] += x * w0.z; acc[i][3] += x * w0.w;
                acc[i][4] += x * w1.x; acc[i][5] += x * w1.y;
                acc[i][6] += x * w1.z; acc[i][7] += x * w1.w;
            }
        }
    }
#pragma unroll
    for (int i = 0; i < 4; ++i) {
        float* dst = g_gpart + ((size_t)(sel * 8 + kp) * 64 + ty * 4 + i) * 3072
                   + nt + tx * 8;
#pragma unroll
        for (int j = 0; j < 8; ++j) dst[j] = acc[i][j];
    }
}

// ---------------------------------------------------------------------------
// GRU gating
// ---------------------------------------------------------------------------
__global__ void k_gru_gate(const float* __restrict__ hst,
                           const float* __restrict__ b_ih,
                           const float* __restrict__ b_hh,
                           float* __restrict__ out)
{
    int idx = blockIdx.x * 256 + threadIdx.x;
    int b = idx >> 10, j = idx & 1023;
    float gi_r = 0.f, gi_z = 0.f, gi_n = 0.f;
    float gh_r = 0.f, gh_z = 0.f, gh_n = 0.f;
#pragma unroll
    for (int kp = 0; kp < 8; ++kp) {
        const float* pi = g_gpart + ((size_t)kp * 64 + b) * 3072;
        const float* ph = g_gpart + ((size_t)(8 + kp) * 64 + b) * 3072;
        gi_r += pi[j]; gi_z += pi[j + 1024]; gi_n += pi[j + 2048];
        gh_r += ph[j]; gh_z += ph[j + 1024]; gh_n += ph[j + 2048];
    }
    gi_r += b_ih[j]; gi_z += b_ih[j + 1024]; gi_n += b_ih[j + 2048];
    gh_r += b_hh[j]; gh_z += b_hh[j + 1024]; gh_n += b_hh[j + 2048];
    float r = sigmoidf_(gi_r + gh_r);
    float z = sigmoidf_(gi_z + gh_z);
    float n = tanhf(gi_n + r * gh_n);
    out[idx] = (1.f - z) * n + z * hst[idx];
}

// ---------------------------------------------------------------------------
// processed_query, split-K=32 batch-tiled: partial[kp][b][a]
// grid (4 ntiles of 128, 32 kp), block 256
// ---------------------------------------------------------------------------
__global__ __launch_bounds__(256) void k_pq_g(
    const float* __restrict__ rnn, const float* __restrict__ q_w)
{
    __shared__ float Xs[64 * 36];
    __shared__ float Ws[32 * 132];

    int tid = threadIdx.x;
    int nt = blockIdx.x * 128;
    int kb = blockIdx.y * 32;

    int ty = tid >> 4, tx = tid & 15;
    int r0 = tid >> 3, c8 = tid & 7;

    float acc[4][8];
#pragma unroll
    for (int i = 0; i < 4; ++i)
#pragma unroll
        for (int j = 0; j < 8; ++j) acc[i][j] = 0.f;

#pragma unroll
    for (int p = 0; p < 2; ++p) {
        int row = r0 + p * 32;
        *(float4*)&Xs[row * 36 + c8 * 4] = *(const float4*)(rnn + row * 1024 + kb + c8 * 4);
    }
#pragma unroll
    for (int p = 0; p < 4; ++p) {
        int j = r0 + p * 32;
        float4 w = *(const float4*)&q_w[(size_t)(nt + j) * 1024 + kb + c8 * 4];
        Ws[(c8 * 4 + 0) * 132 + j] = w.x;
        Ws[(c8 * 4 + 1) * 132 + j] = w.y;
        Ws[(c8 * 4 + 2) * 132 + j] = w.z;
        Ws[(c8 * 4 + 3) * 132 + j] = w.w;
    }
    __syncthreads();
#pragma unroll
    for (int k = 0; k < 32; ++k) {
        float4 w0 = *(const float4*)&Ws[k * 132 + tx * 8];
        float4 w1 = *(const float4*)&Ws[k * 132 + tx * 8 + 4];
#pragma unroll
        for (int i = 0; i < 4; ++i) {
            float x = Xs[(ty * 4 + i) * 36 + k];
            acc[i][0] += x * w0.x; acc[i][1] += x * w0.y;
            acc[i][2] += x * w0.z; acc[i][3] += x * w0.w;
            acc[i][4] += x * w1.x; acc[i][5] += x * w1.y;
            acc[i][6] += x * w1.z; acc[i][7] += x * w1.w;
        }
    }
#pragma unroll
    for (int i = 0; i < 4; ++i) {
        float* dst = g_pqpart + ((size_t)blockIdx.y * 64 + ty * 4 + i) * 512
                   + nt + tx * 8;
#pragma unroll
        for (int j = 0; j < 8; ++j) dst[j] = acc[i][j];
    }
}

__global__ void k_pq_comb(const float* __restrict__ q_b)
{
    int idx = blockIdx.x * 256 + threadIdx.x;  // 32768
    int a = idx & 511;
    float s = q_b[a];
#pragma unroll
    for (int kp = 0; kp < 32; ++kp) s += g_pqpart[kp * 32768 + idx];
    g_pq[idx] = s;
}

// ---------------------------------------------------------------------------
// location conv -> g_lconvh[b][t][f] (half)
// ---------------------------------------------------------------------------
__global__ __launch_bounds__(256) void k_conv(
    const float* __restrict__ atten, const float* __restrict__ conv_w)
{
    __shared__ float sA[2 * 1056];
    __shared__ float sW[16 * 62];
    int b = blockIdx.x, fg = blockIdx.y;
    int tid = threadIdx.x;
    for (int i = tid; i < 2 * 1056; i += 256) {
        int c = i / 1056;
        int p = i % 1056;
        int t = p - 15;
        float v = 0.f;
        if (t >= 0 && t < 1024) v = atten[b * 2048 + c * 1024 + t];
        sA[i] = v;
    }
    for (int i = tid; i < 16 * 62; i += 256) {
        int fo = i / 62, r = i % 62;
        sW[i] = conv_w[(fg * 16 + fo) * 62 + r];
    }
    __syncthreads();
#pragma unroll
    for (int p = 0; p < 4; ++p) {
        int t = tid + p * 256;
        float acc[16];
#pragma unroll
        for (int f = 0; f < 16; ++f) acc[f] = 0.f;
#pragma unroll
        for (int c = 0; c < 2; ++c)
#pragma unroll
            for (int k = 0; k < 31; ++k) {
                float a = sA[c * 1056 + t + k];
#pragma unroll
                for (int f = 0; f < 16; ++f) acc[f] += a * sW[f * 62 + c * 31 + k];
            }
        __half* dst = g_lconvh + (size_t)b * 32768 + t * 32 + fg * 16;
        uint4 o0, o1;
        o0.x = pack_h2(acc[0], acc[1]);   o0.y = pack_h2(acc[2], acc[3]);
        o0.z = pack_h2(acc[4], acc[5]);   o0.w = pack_h2(acc[6], acc[7]);
        o1.x = pack_h2(acc[8], acc[9]);   o1.y = pack_h2(acc[10], acc[11]);
        o1.z = pack_h2(acc[12], acc[13]); o1.w = pack_h2(acc[14], acc[15]);
        *reinterpret_cast<uint4*>(dst) = o0;
        *reinterpret_cast<uint4*>(dst + 8) = o1;
    }
}

// ---------------------------------------------------------------------------
// Energy GEMM, f16 mma.sync m16n8k16 + cp.async double-buffered pipeline.
// Block tile 128t x 128a, 8 warps (4x2). K = 8 chunks of 64 (annot) + 1 of 32 (conv).
// grid (4, 512), block 256, dynamic smem.
// ---------------------------------------------------------------------------
#define EPADH 72                       // halves per smem row (144B, conflict-free)
#define ETILEH (128 * EPADH)           // halves per tile
#define E_SMEM_BYTES (4 * ETILEH * 2 + 1024)

__global__ __launch_bounds__(256) void k_energy(
    const float* __restrict__ a_b, const float* __restrict__ loc_b,
    const float* __restrict__ v_w)
{
    extern __shared__ char smem[];
    __half* Ah[2] = { (__half*)smem,                    (__half*)(smem + 2 * ETILEH * 2) };
    __half* Bh[2] = { (__half*)(smem + ETILEH * 2),     (__half*)(smem + 3 * ETILEH * 2) };
    float* c_s = (float*)(smem + 4 * ETILEH * 2);
    float* v_s = c_s + 128;

    int tid = threadIdx.x;
    int warp = tid >> 5, lane = tid & 31;
    int wm = warp >> 1, wn = warp & 1;
    int g = lane >> 2, tg = lane & 3;

    int atile = blockIdx.x;
    int mtile = blockIdx.y;
    int b = mtile >> 3;
    int t0 = (mtile & 7) << 7;
    int abase = atile << 7;

    if (tid < 128) {
        int a = abase + tid;
        c_s[tid] = g_pq[b * 512 + a] + a_b[a] + loc_b[a];
        v_s[tid] = v_w[a];
    }

    const __half* baseA = g_annots_h + ((size_t)(b * 1024 + t0)) * 512;
    const __half* baseB = g_awh + (size_t)abase * 512;
    const __half* convA = g_lconvh + (size_t)b * 32768 + (size_t)t0 * 32;
    const __half* convB = g_locwh + (size_t)abase * 32;

    auto issue = [&](int kc, int bf) {
        if (kc < 8) {
            const __half* gA = baseA + kc * 64;
            const __half* gB = baseB + kc * 64;
#pragma unroll
            for (int p = 0; p < 4; ++p) {
                int lin = tid + p * 256;
                int row = lin >> 3, seg = lin & 7;
                cp_async16(&Ah[bf][row * EPADH + seg * 8], gA + (size_t)row * 512 + seg * 8);
            }
#pragma unroll
            for (int p = 0; p < 4; ++p) {
                int lin = tid + p * 256;
                int row = lin >> 3, seg = lin & 7;
                cp_async16(&Bh[bf][row * EPADH + seg * 8], gB + (size_t)row * 512 + seg * 8);
            }
        } else {
#pragma unroll
            for (int p = 0; p < 2; ++p) {
                int lin = tid + p * 256;
                int row = lin >> 2, seg = lin & 3;
                cp_async16(&Ah[bf][row * EPADH + seg * 8], convA + (size_t)row * 32 + seg * 8);
            }
#pragma unroll
            for (int p = 0; p < 2; ++p) {
                int lin = tid + p * 256;
                int row = lin >> 2, seg = lin & 3;
                cp_async16(&Bh[bf][row * EPADH + seg * 8], convB + (size_t)row * 32 + seg * 8);
            }
        }
        cp_commit();
    };

    float acc[2][8][4];
#pragma unroll
    for (int mf = 0; mf < 2; ++mf)
#pragma unroll
        for (int nf = 0; nf < 8; ++nf)
#pragma unroll
            for (int q = 0; q < 4; ++q) acc[mf][nf][q] = 0.f;

    issue(0, 0);

    for (int kc = 0; kc < 9; ++kc) {
        int bf = kc & 1;
        if (kc + 1 < 9) {
            issue(kc + 1, bf ^ 1);
            cp_wait<1>();
        } else {
            cp_wait<0>();
        }
        __syncthreads();

        const __half* AA = Ah[bf];
        const __half* BB = Bh[bf];
        int nks = (kc < 8) ? 4 : 2;
#pragma unroll
        for (int ks = 0; ks < 4; ++ks) {
            if (ks >= nks) break;
            int k0 = ks * 16;
            unsigned a_frag[2][4];
#pragma unroll
            for (int mf = 0; mf < 2; ++mf) {
                int rb = wm * 32 + mf * 16;
                a_frag[mf][0] = *(const unsigned*)(AA + (rb + g) * EPADH + k0 + 2 * tg);
                a_frag[mf][1] = *(const unsigned*)(AA + (rb + g + 8) * EPADH + k0 + 2 * tg);
                a_frag[mf][2] = *(const unsigned*)(AA + (rb + g) * EPADH + k0 + 8 + 2 * tg);
                a_frag[mf][3] = *(const unsigned*)(AA + (rb + g + 8) * EPADH + k0 + 8 + 2 * tg);
            }
#pragma unroll
            for (int nf = 0; nf < 8; ++nf) {
                int ar = wn * 64 + nf * 8 + g;
                unsigned b0 = *(const unsigned*)(BB + ar * EPADH + k0 + 2 * tg);
                unsigned b1 = *(const unsigned*)(BB + ar * EPADH + k0 + 8 + 2 * tg);
                mma_f16(acc[0][nf], a_frag[0], b0, b1);
                mma_f16(acc[1][nf], a_frag[1], b0, b1);
            }
        }
        __syncthreads();
    }

    // epilogue: bias + tanh + v-weight, reduce over a within warp
#pragma unroll
    for (int mf = 0; mf < 2; ++mf) {
#pragma unroll
        for (int rh = 0; rh < 2; ++rh) {
            float s = 0.f;
#pragma unroll
            for (int nf = 0; nf < 8; ++nf) {
                int a0 = wn * 64 + nf * 8 + 2 * tg;
                float x = acc[mf][nf][rh * 2 + 0] + c_s[a0];
                float y = acc[mf][nf][rh * 2 + 1] + c_s[a0 + 1];
                s += v_s[a0] * tanh_fast(x) + v_s[a0 + 1] * tanh_fast(y);
            }
            s += __shfl_xor_sync(0xffffffffu, s, 1);
            s += __shfl_xor_sync(0xffffffffu, s, 2);
            if (tg == 0) {
                int t = t0 + wm * 32 + mf * 16 + rh * 8 + g;
                g_part[((size_t)(atile * 2 + wn) * 64 + b) * 1024 + t] = s;
            }
        }
    }
}

// ---------------------------------------------------------------------------
// mask + sigmoid + row normalize -> alignment
// ---------------------------------------------------------------------------
__global__ void k_norm(const int* __restrict__ mask, float* __restrict__ out)
{
    int b = blockIdx.x, tid = threadIdx.x;
    __shared__ float red[256];
    float s[4];
    float loc = 0.f;
#pragma unroll
    for (int i = 0; i < 4; ++i) {
        int t = tid + i * 256;
        float raw = 0.f;
#pragma unroll
        for (int sl = 0; sl < 8; ++sl) raw += g_part[sl * 65536 + b * 1024 + t];
        float v = (mask[b * 1024 + t] != 0) ? 1.f / (1.f + expf(-raw)) : 0.f;
        s[i] = v;
        loc += v;
    }
    red[tid] = loc;
    __syncthreads();
    for (int st = 128; st; st >>= 1) {
        if (tid < st) red[tid] += red[tid + st];
        __syncthreads();
    }
    float inv = 1.f / red[0];
#pragma unroll
    for (int i = 0; i < 4; ++i)
        out[98304 + b * 1024 + tid + i * 256] = s[i] * inv;
}

// ---------------------------------------------------------------------------
// new_context[b,d] = sum_t align[b,t] * annots[b,t,d]
// ---------------------------------------------------------------------------
__global__ __launch_bounds__(512) void k_ctx(
    const float* __restrict__ annots, const float* __restrict__ align,
    float* __restrict__ outc)
{
    __shared__ float w[1024];
    __shared__ float red[512];
    int b = blockIdx.y, d0 = blockIdx.x * 128;
    int tid = threadIdx.x;
    for (int i = tid; i < 1024; i += 512) w[i] = align[b * 1024 + i];
    __syncthreads();
    int d = d0 + (tid & 127);
    int part = tid >> 7;
    const float* A = annots + (size_t)(b * 1024 + part * 256) * 512 + d;
    float acc = 0.f;
#pragma unroll 8
    for (int t = 0; t < 256; ++t) acc += w[part * 256 + t] * A[(size_t)t * 512];
    red[tid] = acc;
    __syncthreads();
    if (part == 0)
        outc[b * 512 + d] = red[tid] + red[tid + 128] + red[tid + 256] + red[tid + 384];
}

// ---------------------------------------------------------------------------
extern "C" void kernel_launch(void* const* d_in, const int* in_sizes, int n_in,
                              void* d_out, int out_size)
{
    const float* memory    = (const float*)d_in[0];
    const float* context   = (const float*)d_in[1];
    const float* rnn_state = (const float*)d_in[2];
    const float* annots    = (const float*)d_in[3];
    const float* atten     = (const float*)d_in[4];
    const int*   mask      = (const int*)d_in[5];

    int w = 6;
    if (n_in >= 19 && in_sizes[6] == 1) w = 7;

    const float* W_ih   = (const float*)d_in[w + 0];
    const float* W_hh   = (const float*)d_in[w + 1];
    const float* b_ih   = (const float*)d_in[w + 2];
    const float* b_hh   = (const float*)d_in[w + 3];
    const float* conv_w = (const float*)d_in[w + 4];
    const float* loc_w  = (const float*)d_in[w + 5];
    const float* loc_b  = (const float*)d_in[w + 6];
    const float* q_w    = (const float*)d_in[w + 7];
    const float* q_b    = (const float*)d_in[w + 8];
    const float* a_w    = (const float*)d_in[w + 9];
    const float* a_b    = (const float*)d_in[w + 10];
    const float* v_w    = (const float*)d_in[w + 11];

    float* out = (float*)d_out;
    // layout: [rnn_output 64*1024][new_context 64*512][alignment 64*1024]

    static int smem_set = 0;
    if (!smem_set) {
        cudaFuncSetAttribute(k_energy, cudaFuncAttributeMaxDynamicSharedMemorySize,
                             E_SMEM_BYTES);
        smem_set = 1;
    }

    k_cvt_annots<<<16384, 256>>>(annots);
    k_cvt_w<<<136, 256>>>(a_w, loc_w);
    k_gru_gemm<<<dim3(24, 8, 2), 256>>>(memory, context, rnn_state, W_ih, W_hh);
    k_conv<<<dim3(64, 2), 256>>>(atten, conv_w);
    k_gru_gate<<<256, 256>>>(rnn_state, b_ih, b_hh, out);
    k_pq_g<<<dim3(4, 32), 256>>>(out, q_w);
    k_pq_comb<<<128, 256>>>(q_b);
    k_energy<<<dim3(4, 512), 256, E_SMEM_BYTES>>>(a_b, loc_b, v_w);
    k_norm<<<64, 256>>>(mask, out);
    k_ctx<<<dim3(4, 64), 512>>>(annots, out + 98304, out + 65536);
}

// round 11
// speedup vs baseline: 1.0122x; 1.0069x over previous
#include <cuda_runtime.h>
#include <cuda_fp16.h>
#include <cstdint>
#include <math.h>

// dims: B=64, T=1024, ANNOT=512, RNN=1024, MEM=512, ATTN=512, FILTERS=32, KSIZE=31
// outputs: rnn_output[64,1024] | new_context[64,512] | alignment[64,1024] (float32)

__device__ float g_gpart[2 * 8 * 64 * 3072];   // [sel][kpart][b][j]
__device__ float g_pqpart[32 * 64 * 512];      // [kp][b][a]
__device__ float g_pq[64 * 512];
__device__ float g_part[8 * 64 * 1024];        // [atile*2+wn][b][t]

__device__ __half g_annots_h[64 * 1024 * 512]; // [b][t][d]  (64 MB)
__device__ __half g_awh[512 * 512];            // [a][d]
__device__ __half g_locwh[512 * 32];           // [a][f]
__device__ __half g_lconvh[64 * 1024 * 32];    // [b][t][f]

__device__ __forceinline__ float sigmoidf_(float x) { return 1.f / (1.f + expf(-x)); }

__device__ __forceinline__ float tanh_fast(float x) {
    float y;
    asm("tanh.approx.f32 %0, %1;" : "=f"(y) : "f"(x));
    return y;
}

__device__ __forceinline__ void mma_f16(float* d, const unsigned* a,
                                        unsigned b0, unsigned b1) {
    asm volatile(
        "mma.sync.aligned.m16n8k16.row.col.f32.f16.f16.f32 "
        "{%0,%1,%2,%3}, {%4,%5,%6,%7}, {%8,%9}, {%0,%1,%2,%3};"
        : "+f"(d[0]), "+f"(d[1]), "+f"(d[2]), "+f"(d[3])
        : "r"(a[0]), "r"(a[1]), "r"(a[2]), "r"(a[3]), "r"(b0), "r"(b1));
}

__device__ __forceinline__ void cp_async16(void* smem_dst, const void* gmem_src) {
    uint32_t s;
    asm("{ .reg .u64 t; cvta.to.shared.u64 t, %1; cvt.u32.u64 %0, t; }"
        : "=r"(s) : "l"(smem_dst));
    asm volatile("cp.async.ca.shared.global [%0], [%1], 16;" :: "r"(s), "l"(gmem_src));
}
__device__ __forceinline__ void cp_commit() {
    asm volatile("cp.async.commit_group;");
}
template <int N>
__device__ __forceinline__ void cp_wait() {
    asm volatile("cp.async.wait_group %0;" :: "n"(N));
}

__device__ __forceinline__ unsigned pack_h2(float a, float b) {
    __half2 h = __floats2half2_rn(a, b);
    return *reinterpret_cast<unsigned*>(&h);
}

// ---------------------------------------------------------------------------
// fp32 -> fp16 conversion passes
// ---------------------------------------------------------------------------
__global__ __launch_bounds__(256) void k_cvt_annots(const float* __restrict__ src)
{
    size_t i = ((size_t)blockIdx.x * 256 + threadIdx.x) * 8;   // 33.5M elements
    float4 x = *(const float4*)(src + i);
    float4 y = *(const float4*)(src + i + 4);
    uint4 o;
    o.x = pack_h2(x.x, x.y); o.y = pack_h2(x.z, x.w);
    o.z = pack_h2(y.x, y.y); o.w = pack_h2(y.z, y.w);
    *reinterpret_cast<uint4*>(&g_annots_h[i]) = o;
}

__global__ __launch_bounds__(256) void k_cvt_w(const float* __restrict__ a_w,
                                               const float* __restrict__ loc_w)
{
    int bx = blockIdx.x;
    const float* src; __half* dst; size_t base;
    if (bx < 128) { src = a_w;  dst = g_awh;   base = (size_t)bx * 2048; }
    else          { src = loc_w; dst = g_locwh; base = (size_t)(bx - 128) * 2048; }
    size_t i = base + threadIdx.x * 8;
    float4 x = *(const float4*)(src + i);
    float4 y = *(const float4*)(src + i + 4);
    uint4 o;
    o.x = pack_h2(x.x, x.y); o.y = pack_h2(x.z, x.w);
    o.z = pack_h2(y.x, y.y); o.w = pack_h2(y.z, y.w);
    *reinterpret_cast<uint4*>(&dst[i]) = o;
}

// ---------------------------------------------------------------------------
// GRU GEMMs, batch-tiled split-K (K=1024 both). grid (24, 8, 2), block 256.
// ---------------------------------------------------------------------------
__global__ __launch_bounds__(256) void k_gru_gemm(
    const float* __restrict__ mem, const float* __restrict__ ctx,
    const float* __restrict__ hst,
    const float* __restrict__ W_ih, const float* __restrict__ W_hh)
{
    __shared__ float Xs[64 * 36];
    __shared__ float Ws[32 * 132];

    int tid = threadIdx.x;
    int nt = blockIdx.x * 128;
    int kp = blockIdx.y;
    int sel = blockIdx.z;
    const int K = 1024;
    const int klen = 128;
    int kbeg = kp * klen;
    const float* W = sel ? W_hh : W_ih;

    int ty = tid >> 4, tx = tid & 15;
    int r0 = tid >> 3, c8 = tid & 7;

    float acc[4][8];
#pragma unroll
    for (int i = 0; i < 4; ++i)
#pragma unroll
        for (int j = 0; j < 8; ++j) acc[i][j] = 0.f;

    for (int kb = kbeg; kb < kbeg + klen; kb += 32) {
        __syncthreads();
#pragma unroll
        for (int p = 0; p < 2; ++p) {
            int row = r0 + p * 32;
            int k = kb + c8 * 4;
            const float* src;
            if (sel) src = hst + row * 1024 + k;
            else src = (k < 512) ? mem + row * 512 + k
                                 : ctx + row * 512 + (k - 512);
            *(float4*)&Xs[row * 36 + c8 * 4] = *(const float4*)src;
        }
#pragma unroll
        for (int p = 0; p < 4; ++p) {
            int j = r0 + p * 32;
            float4 w = *(const float4*)&W[(size_t)(nt + j) * K + kb + c8 * 4];
            Ws[(c8 * 4 + 0) * 132 + j] = w.x;
            Ws[(c8 * 4 + 1) * 132 + j] = w.y;
            Ws[(c8 * 4 + 2) * 132 + j] = w.z;
            Ws[(c8 * 4 + 3) * 132 + j] = w.w;
        }
        __syncthreads();
#pragma unroll
        for (int k = 0; k < 32; ++k) {
            float4 w0 = *(const float4*)&Ws[k * 132 + tx * 8];
            float4 w1 = *(const float4*)&Ws[k * 132 + tx * 8 + 4];
#pragma unroll
            for (int i = 0; i < 4; ++i) {
                float x = Xs[(ty * 4 + i) * 36 + k];
                acc[i][0] += x * w0.x; acc[i][1] += x * w0.y;
                acc[i][2] += x * w0.z; acc[i][3] += x * w0.w;
                acc[i][4] += x * w1.x; acc[i][5] += x * w1.y;
                acc[i][6] += x * w1.z; acc[i][7] += x * w1.w;
            }
        }
    }
#pragma unroll
    for (int i = 0; i < 4; ++i) {
        float* dst = g_gpart + ((size_t)(sel * 8 + kp) * 64 + ty * 4 + i) * 3072
                   + nt + tx * 8;
#pragma unroll
        for (int j = 0; j < 8; ++j) dst[j] = acc[i][j];
    }
}

// ---------------------------------------------------------------------------
// GRU gating
// ---------------------------------------------------------------------------
__global__ void k_gru_gate(const float* __restrict__ hst,
                           const float* __restrict__ b_ih,
                           const float* __restrict__ b_hh,
                           float* __restrict__ out)
{
    int idx = blockIdx.x * 256 + threadIdx.x;
    int b = idx >> 10, j = idx & 1023;
    float gi_r = 0.f, gi_z = 0.f, gi_n = 0.f;
    float gh_r = 0.f, gh_z = 0.f, gh_n = 0.f;
#pragma unroll
    for (int kp = 0; kp < 8; ++kp) {
        const float* pi = g_gpart + ((size_t)kp * 64 + b) * 3072;
        const float* ph = g_gpart + ((size_t)(8 + kp) * 64 + b) * 3072;
        gi_r += pi[j]; gi_z += pi[j + 1024]; gi_n += pi[j + 2048];
        gh_r += ph[j]; gh_z += ph[j + 1024]; gh_n += ph[j + 2048];
    }
    gi_r += b_ih[j]; gi_z += b_ih[j + 1024]; gi_n += b_ih[j + 2048];
    gh_r += b_hh[j]; gh_z += b_hh[j + 1024]; gh_n += b_hh[j + 2048];
    float r = sigmoidf_(gi_r + gh_r);
    float z = sigmoidf_(gi_z + gh_z);
    float n = tanhf(gi_n + r * gh_n);
    out[idx] = (1.f - z) * n + z * hst[idx];
}

// ---------------------------------------------------------------------------
// processed_query, split-K=32 batch-tiled: partial[kp][b][a]
// grid (4 ntiles of 128, 32 kp), block 256
// ---------------------------------------------------------------------------
__global__ __launch_bounds__(256) void k_pq_g(
    const float* __restrict__ rnn, const float* __restrict__ q_w)
{
    __shared__ float Xs[64 * 36];
    __shared__ float Ws[32 * 132];

    int tid = threadIdx.x;
    int nt = blockIdx.x * 128;
    int kb = blockIdx.y * 32;

    int ty = tid >> 4, tx = tid & 15;
    int r0 = tid >> 3, c8 = tid & 7;

    float acc[4][8];
#pragma unroll
    for (int i = 0; i < 4; ++i)
#pragma unroll
        for (int j = 0; j < 8; ++j) acc[i][j] = 0.f;

#pragma unroll
    for (int p = 0; p < 2; ++p) {
        int row = r0 + p * 32;
        *(float4*)&Xs[row * 36 + c8 * 4] = *(const float4*)(rnn + row * 1024 + kb + c8 * 4);
    }
#pragma unroll
    for (int p = 0; p < 4; ++p) {
        int j = r0 + p * 32;
        float4 w = *(const float4*)&q_w[(size_t)(nt + j) * 1024 + kb + c8 * 4];
        Ws[(c8 * 4 + 0) * 132 + j] = w.x;
        Ws[(c8 * 4 + 1) * 132 + j] = w.y;
        Ws[(c8 * 4 + 2) * 132 + j] = w.z;
        Ws[(c8 * 4 + 3) * 132 + j] = w.w;
    }
    __syncthreads();
#pragma unroll
    for (int k = 0; k < 32; ++k) {
        float4 w0 = *(const float4*)&Ws[k * 132 + tx * 8];
        float4 w1 = *(const float4*)&Ws[k * 132 + tx * 8 + 4];
#pragma unroll
        for (int i = 0; i < 4; ++i) {
            float x = Xs[(ty * 4 + i) * 36 + k];
            acc[i][0] += x * w0.x; acc[i][1] += x * w0.y;
            acc[i][2] += x * w0.z; acc[i][3] += x * w0.w;
            acc[i][4] += x * w1.x; acc[i][5] += x * w1.y;
            acc[i][6] += x * w1.z; acc[i][7] += x * w1.w;
        }
    }
#pragma unroll
    for (int i = 0; i < 4; ++i) {
        float* dst = g_pqpart + ((size_t)blockIdx.y * 64 + ty * 4 + i) * 512
                   + nt + tx * 8;
#pragma unroll
        for (int j = 0; j < 8; ++j) dst[j] = acc[i][j];
    }
}

__global__ void k_pq_comb(const float* __restrict__ q_b)
{
    int idx = blockIdx.x * 256 + threadIdx.x;  // 32768
    int a = idx & 511;
    float s = q_b[a];
#pragma unroll
    for (int kp = 0; kp < 32; ++kp) s += g_pqpart[kp * 32768 + idx];
    g_pq[idx] = s;
}

// ---------------------------------------------------------------------------
// location conv -> g_lconvh[b][t][f] (half)
// ---------------------------------------------------------------------------
__global__ __launch_bounds__(256) void k_conv(
    const float* __restrict__ atten, const float* __restrict__ conv_w)
{
    __shared__ float sA[2 * 1056];
    __shared__ float sW[16 * 62];
    int b = blockIdx.x, fg = blockIdx.y;
    int tid = threadIdx.x;
    for (int i = tid; i < 2 * 1056; i += 256) {
        int c = i / 1056;
        int p = i % 1056;
        int t = p - 15;
        float v = 0.f;
        if (t >= 0 && t < 1024) v = atten[b * 2048 + c * 1024 + t];
        sA[i] = v;
    }
    for (int i = tid; i < 16 * 62; i += 256) {
        int fo = i / 62, r = i % 62;
        sW[i] = conv_w[(fg * 16 + fo) * 62 + r];
    }
    __syncthreads();
#pragma unroll
    for (int p = 0; p < 4; ++p) {
        int t = tid + p * 256;
        float acc[16];
#pragma unroll
        for (int f = 0; f < 16; ++f) acc[f] = 0.f;
#pragma unroll
        for (int c = 0; c < 2; ++c)
#pragma unroll
            for (int k = 0; k < 31; ++k) {
                float a = sA[c * 1056 + t + k];
#pragma unroll
                for (int f = 0; f < 16; ++f) acc[f] += a * sW[f * 62 + c * 31 + k];
            }
        __half* dst = g_lconvh + (size_t)b * 32768 + t * 32 + fg * 16;
        uint4 o0, o1;
        o0.x = pack_h2(acc[0], acc[1]);   o0.y = pack_h2(acc[2], acc[3]);
        o0.z = pack_h2(acc[4], acc[5]);   o0.w = pack_h2(acc[6], acc[7]);
        o1.x = pack_h2(acc[8], acc[9]);   o1.y = pack_h2(acc[10], acc[11]);
        o1.z = pack_h2(acc[12], acc[13]); o1.w = pack_h2(acc[14], acc[15]);
        *reinterpret_cast<uint4*>(dst) = o0;
        *reinterpret_cast<uint4*>(dst + 8) = o1;
    }
}

// ---------------------------------------------------------------------------
// Energy GEMM, f16 mma.sync m16n8k16 + cp.async double-buffered pipeline.
// Block tile 128t x 128a, 8 warps (4x2). K = 8 chunks of 64 (annot) + 1 of 32 (conv).
// grid (4, 512), block 256, dynamic smem.
// ---------------------------------------------------------------------------
#define EPADH 72                       // halves per smem row (144B, conflict-free)
#define ETILEH (128 * EPADH)           // halves per tile
#define E_SMEM_BYTES (4 * ETILEH * 2 + 1024)

__global__ __launch_bounds__(256) void k_energy(
    const float* __restrict__ a_b, const float* __restrict__ loc_b,
    const float* __restrict__ v_w)
{
    extern __shared__ char smem[];
    __half* Ah[2] = { (__half*)smem,                    (__half*)(smem + 2 * ETILEH * 2) };
    __half* Bh[2] = { (__half*)(smem + ETILEH * 2),     (__half*)(smem + 3 * ETILEH * 2) };
    float* c_s = (float*)(smem + 4 * ETILEH * 2);
    float* v_s = c_s + 128;

    int tid = threadIdx.x;
    int warp = tid >> 5, lane = tid & 31;
    int wm = warp >> 1, wn = warp & 1;
    int g = lane >> 2, tg = lane & 3;

    int atile = blockIdx.x;
    int mtile = blockIdx.y;
    int b = mtile >> 3;
    int t0 = (mtile & 7) << 7;
    int abase = atile << 7;

    if (tid < 128) {
        int a = abase + tid;
        c_s[tid] = g_pq[b * 512 + a] + a_b[a] + loc_b[a];
        v_s[tid] = v_w[a];
    }

    const __half* baseA = g_annots_h + ((size_t)(b * 1024 + t0)) * 512;
    const __half* baseB = g_awh + (size_t)abase * 512;
    const __half* convA = g_lconvh + (size_t)b * 32768 + (size_t)t0 * 32;
    const __half* convB = g_locwh + (size_t)abase * 32;

    auto issue = [&](int kc, int bf) {
        if (kc < 8) {
            const __half* gA = baseA + kc * 64;
            const __half* gB = baseB + kc * 64;
#pragma unroll
            for (int p = 0; p < 4; ++p) {
                int lin = tid + p * 256;
                int row = lin >> 3, seg = lin & 7;
                cp_async16(&Ah[bf][row * EPADH + seg * 8], gA + (size_t)row * 512 + seg * 8);
            }
#pragma unroll
            for (int p = 0; p < 4; ++p) {
                int lin = tid + p * 256;
                int row = lin >> 3, seg = lin & 7;
                cp_async16(&Bh[bf][row * EPADH + seg * 8], gB + (size_t)row * 512 + seg * 8);
            }
        } else {
#pragma unroll
            for (int p = 0; p < 2; ++p) {
                int lin = tid + p * 256;
                int row = lin >> 2, seg = lin & 3;
                cp_async16(&Ah[bf][row * EPADH + seg * 8], convA + (size_t)row * 32 + seg * 8);
            }
#pragma unroll
            for (int p = 0; p < 2; ++p) {
                int lin = tid + p * 256;
                int row = lin >> 2, seg = lin & 3;
                cp_async16(&Bh[bf][row * EPADH + seg * 8], convB + (size_t)row * 32 + seg * 8);
            }
        }
        cp_commit();
    };

    float acc[2][8][4];
#pragma unroll
    for (int mf = 0; mf < 2; ++mf)
#pragma unroll
        for (int nf = 0; nf < 8; ++nf)
#pragma unroll
            for (int q = 0; q < 4; ++q) acc[mf][nf][q] = 0.f;

    issue(0, 0);

    for (int kc = 0; kc < 9; ++kc) {
        int bf = kc & 1;
        if (kc + 1 < 9) {
            issue(kc + 1, bf ^ 1);
            cp_wait<1>();
        } else {
            cp_wait<0>();
        }
        __syncthreads();

        const __half* AA = Ah[bf];
        const __half* BB = Bh[bf];
        int nks = (kc < 8) ? 4 : 2;
#pragma unroll
        for (int ks = 0; ks < 4; ++ks) {
            if (ks >= nks) break;
            int k0 = ks * 16;
            unsigned a_frag[2][4];
#pragma unroll
            for (int mf = 0; mf < 2; ++mf) {
                int rb = wm * 32 + mf * 16;
                a_frag[mf][0] = *(const unsigned*)(AA + (rb + g) * EPADH + k0 + 2 * tg);
                a_frag[mf][1] = *(const unsigned*)(AA + (rb + g + 8) * EPADH + k0 + 2 * tg);
                a_frag[mf][2] = *(const unsigned*)(AA + (rb + g) * EPADH + k0 + 8 + 2 * tg);
                a_frag[mf][3] = *(const unsigned*)(AA + (rb + g + 8) * EPADH + k0 + 8 + 2 * tg);
            }
#pragma unroll
            for (int nf = 0; nf < 8; ++nf) {
                int ar = wn * 64 + nf * 8 + g;
                unsigned b0 = *(const unsigned*)(BB + ar * EPADH + k0 + 2 * tg);
                unsigned b1 = *(const unsigned*)(BB + ar * EPADH + k0 + 8 + 2 * tg);
                mma_f16(acc[0][nf], a_frag[0], b0, b1);
                mma_f16(acc[1][nf], a_frag[1], b0, b1);
            }
        }
        __syncthreads();
    }

    // epilogue: bias + tanh + v-weight, reduce over a within warp
#pragma unroll
    for (int mf = 0; mf < 2; ++mf) {
#pragma unroll
        for (int rh = 0; rh < 2; ++rh) {
            float s = 0.f;
#pragma unroll
            for (int nf = 0; nf < 8; ++nf) {
                int a0 = wn * 64 + nf * 8 + 2 * tg;
                float x = acc[mf][nf][rh * 2 + 0] + c_s[a0];
                float y = acc[mf][nf][rh * 2 + 1] + c_s[a0 + 1];
                s += v_s[a0] * tanh_fast(x) + v_s[a0 + 1] * tanh_fast(y);
            }
            s += __shfl_xor_sync(0xffffffffu, s, 1);
            s += __shfl_xor_sync(0xffffffffu, s, 2);
            if (tg == 0) {
                int t = t0 + wm * 32 + mf * 16 + rh * 8 + g;
                g_part[((size_t)(atile * 2 + wn) * 64 + b) * 1024 + t] = s;
            }
        }
    }
}

// ---------------------------------------------------------------------------
// mask + sigmoid + row normalize -> alignment
// ---------------------------------------------------------------------------
__global__ void k_norm(const int* __restrict__ mask, float* __restrict__ out)
{
    int b = blockIdx.x, tid = threadIdx.x;
    __shared__ float red[256];
    float s[4];
    float loc = 0.f;
#pragma unroll
    for (int i = 0; i < 4; ++i) {
        int t = tid + i * 256;
        float raw = 0.f;
#pragma unroll
        for (int sl = 0; sl < 8; ++sl) raw += g_part[sl * 65536 + b * 1024 + t];
        float v = (mask[b * 1024 + t] != 0) ? 1.f / (1.f + expf(-raw)) : 0.f;
        s[i] = v;
        loc += v;
    }
    red[tid] = loc;
    __syncthreads();
    for (int st = 128; st; st >>= 1) {
        if (tid < st) red[tid] += red[tid + st];
        __syncthreads();
    }
    float inv = 1.f / red[0];
#pragma unroll
    for (int i = 0; i < 4; ++i)
        out[98304 + b * 1024 + tid + i * 256] = s[i] * inv;
}

// ---------------------------------------------------------------------------
// new_context[b,d] = sum_t align[b,t] * annots[b,t,d]
// ---------------------------------------------------------------------------
__global__ __launch_bounds__(512) void k_ctx(
    const float* __restrict__ annots, const float* __restrict__ align,
    float* __restrict__ outc)
{
    __shared__ float w[1024];
    __shared__ float red[512];
    int b = blockIdx.y, d0 = blockIdx.x * 128;
    int tid = threadIdx.x;
    for (int i = tid; i < 1024; i += 512) w[i] = align[b * 1024 + i];
    __syncthreads();
    int d = d0 + (tid & 127);
    int part = tid >> 7;
    const float* A = annots + (size_t)(b * 1024 + part * 256) * 512 + d;
    float acc = 0.f;
#pragma unroll 8
    for (int t = 0; t < 256; ++t) acc += w[part * 256 + t] * A[(size_t)t * 512];
    red[tid] = acc;
    __syncthreads();
    if (part == 0)
        outc[b * 512 + d] = red[tid] + red[tid + 128] + red[tid + 256] + red[tid + 384];
}

// ---------------------------------------------------------------------------
extern "C" void kernel_launch(void* const* d_in, const int* in_sizes, int n_in,
                              void* d_out, int out_size)
{
    const float* memory    = (const float*)d_in[0];
    const float* context   = (const float*)d_in[1];
    const float* rnn_state = (const float*)d_in[2];
    const float* annots    = (const float*)d_in[3];
    const float* atten     = (const float*)d_in[4];
    const int*   mask      = (const int*)d_in[5];

    int w = 6;
    if (n_in >= 19 && in_sizes[6] == 1) w = 7;

    const float* W_ih   = (const float*)d_in[w + 0];
    const float* W_hh   = (const float*)d_in[w + 1];
    const float* b_ih   = (const float*)d_in[w + 2];
    const float* b_hh   = (const float*)d_in[w + 3];
    const float* conv_w = (const float*)d_in[w + 4];
    const float* loc_w  = (const float*)d_in[w + 5];
    const float* loc_b  = (const float*)d_in[w + 6];
    const float* q_w    = (const float*)d_in[w + 7];
    const float* q_b    = (const float*)d_in[w + 8];
    const float* a_w    = (const float*)d_in[w + 9];
    const float* a_b    = (const float*)d_in[w + 10];
    const float* v_w    = (const float*)d_in[w + 11];

    float* out = (float*)d_out;
    // layout: [rnn_output 64*1024][new_context 64*512][alignment 64*1024]

    static int smem_set = 0;
    if (!smem_set) {
        cudaFuncSetAttribute(k_energy, cudaFuncAttributeMaxDynamicSharedMemorySize,
                             E_SMEM_BYTES);
        smem_set = 1;
    }

    k_cvt_annots<<<16384, 256>>>(annots);
    k_cvt_w<<<136, 256>>>(a_w, loc_w);
    k_gru_gemm<<<dim3(24, 8, 2), 256>>>(memory, context, rnn_state, W_ih, W_hh);
    k_conv<<<dim3(64, 2), 256>>>(atten, conv_w);
    k_gru_gate<<<256, 256>>>(rnn_state, b_ih, b_hh, out);
    k_pq_g<<<dim3(4, 32), 256>>>(out, q_w);
    k_pq_comb<<<128, 256>>>(q_b);
    k_energy<<<dim3(4, 512), 256, E_SMEM_BYTES>>>(a_b, loc_b, v_w);
    k_norm<<<64, 256>>>(mask, out);
    k_ctx<<<dim3(4, 64), 512>>>(annots, out + 98304, out + 65536);
}

// round 12
// speedup vs baseline: 1.0124x; 1.0002x over previous
#include <cuda_runtime.h>
#include <cuda_fp16.h>
#include <cstdint>
#include <math.h>

// dims: B=64, T=1024, ANNOT=512, RNN=1024, MEM=512, ATTN=512, FILTERS=32, KSIZE=31
// outputs: rnn_output[64,1024] | new_context[64,512] | alignment[64,1024] (float32)

__device__ float g_gpart[2 * 8 * 64 * 3072];   // [sel][kpart][b][j]
__device__ float g_pqpart[32 * 64 * 512];      // [kp][b][a]
__device__ float g_pq[64 * 512];
__device__ float g_part[8 * 64 * 1024];        // [atile*2+wn][b][t]

__device__ __half g_annots_h[64 * 1024 * 512]; // [b][t][d]  (64 MB)
__device__ __half g_awh[512 * 512];            // [a][d]
__device__ __half g_locwh[512 * 32];           // [a][f]
__device__ __half g_lconvh[64 * 1024 * 32];    // [b][t][f]

__device__ __forceinline__ float sigmoidf_(float x) { return 1.f / (1.f + expf(-x)); }

__device__ __forceinline__ float tanh_fast(float x) {
    float y;
    asm("tanh.approx.f32 %0, %1;" : "=f"(y) : "f"(x));
    return y;
}

__device__ __forceinline__ void mma_f16(float* d, const unsigned* a,
                                        unsigned b0, unsigned b1) {
    asm volatile(
        "mma.sync.aligned.m16n8k16.row.col.f32.f16.f16.f32 "
        "{%0,%1,%2,%3}, {%4,%5,%6,%7}, {%8,%9}, {%0,%1,%2,%3};"
        : "+f"(d[0]), "+f"(d[1]), "+f"(d[2]), "+f"(d[3])
        : "r"(a[0]), "r"(a[1]), "r"(a[2]), "r"(a[3]), "r"(b0), "r"(b1));
}

__device__ __forceinline__ void cp_async16(void* smem_dst, const void* gmem_src) {
    uint32_t s;
    asm("{ .reg .u64 t; cvta.to.shared.u64 t, %1; cvt.u32.u64 %0, t; }"
        : "=r"(s) : "l"(smem_dst));
    asm volatile("cp.async.ca.shared.global [%0], [%1], 16;" :: "r"(s), "l"(gmem_src));
}
__device__ __forceinline__ void cp_commit() {
    asm volatile("cp.async.commit_group;");
}
template <int N>
__device__ __forceinline__ void cp_wait() {
    asm volatile("cp.async.wait_group %0;" :: "n"(N));
}

__device__ __forceinline__ unsigned pack_h2(float a, float b) {
    __half2 h = __floats2half2_rn(a, b);
    return *reinterpret_cast<unsigned*>(&h);
}

// ---------------------------------------------------------------------------
// fp32 -> fp16 conversion passes
// ---------------------------------------------------------------------------
__global__ __launch_bounds__(256) void k_cvt_annots(const float* __restrict__ src)
{
    size_t i = ((size_t)blockIdx.x * 256 + threadIdx.x) * 8;   // 33.5M elements
    float4 x = *(const float4*)(src + i);
    float4 y = *(const float4*)(src + i + 4);
    uint4 o;
    o.x = pack_h2(x.x, x.y); o.y = pack_h2(x.z, x.w);
    o.z = pack_h2(y.x, y.y); o.w = pack_h2(y.z, y.w);
    *reinterpret_cast<uint4*>(&g_annots_h[i]) = o;
}

__global__ __launch_bounds__(256) void k_cvt_w(const float* __restrict__ a_w,
                                               const float* __restrict__ loc_w)
{
    int bx = blockIdx.x;
    const float* src; __half* dst; size_t base;
    if (bx < 128) { src = a_w;  dst = g_awh;   base = (size_t)bx * 2048; }
    else          { src = loc_w; dst = g_locwh; base = (size_t)(bx - 128) * 2048; }
    size_t i = base + threadIdx.x * 8;
    float4 x = *(const float4*)(src + i);
    float4 y = *(const float4*)(src + i + 4);
    uint4 o;
    o.x = pack_h2(x.x, x.y); o.y = pack_h2(x.z, x.w);
    o.z = pack_h2(y.x, y.y); o.w = pack_h2(y.z, y.w);
    *reinterpret_cast<uint4*>(&dst[i]) = o;
}

// ---------------------------------------------------------------------------
// GRU GEMMs, batch-tiled split-K (K=1024 both). grid (24, 8, 2), block 256.
// ---------------------------------------------------------------------------
__global__ __launch_bounds__(256) void k_gru_gemm(
    const float* __restrict__ mem, const float* __restrict__ ctx,
    const float* __restrict__ hst,
    const float* __restrict__ W_ih, const float* __restrict__ W_hh)
{
    __shared__ float Xs[64 * 36];
    __shared__ float Ws[32 * 132];

    int tid = threadIdx.x;
    int nt = blockIdx.x * 128;
    int kp = blockIdx.y;
    int sel = blockIdx.z;
    const int K = 1024;
    const int klen = 128;
    int kbeg = kp * klen;
    const float* W = sel ? W_hh : W_ih;

    int ty = tid >> 4, tx = tid & 15;
    int r0 = tid >> 3, c8 = tid & 7;

    float acc[4][8];
#pragma unroll
    for (int i = 0; i < 4; ++i)
#pragma unroll
        for (int j = 0; j < 8; ++j) acc[i][j] = 0.f;

    for (int kb = kbeg; kb < kbeg + klen; kb += 32) {
        __syncthreads();
#pragma unroll
        for (int p = 0; p < 2; ++p) {
            int row = r0 + p * 32;
            int k = kb + c8 * 4;
            const float* src;
            if (sel) src = hst + row * 1024 + k;
            else src = (k < 512) ? mem + row * 512 + k
                                 : ctx + row * 512 + (k - 512);
            *(float4*)&Xs[row * 36 + c8 * 4] = *(const float4*)src;
        }
#pragma unroll
        for (int p = 0; p < 4; ++p) {
            int j = r0 + p * 32;
            float4 w = *(const float4*)&W[(size_t)(nt + j) * K + kb + c8 * 4];
            Ws[(c8 * 4 + 0) * 132 + j] = w.x;
            Ws[(c8 * 4 + 1) * 132 + j] = w.y;
            Ws[(c8 * 4 + 2) * 132 + j] = w.z;
            Ws[(c8 * 4 + 3) * 132 + j] = w.w;
        }
        __syncthreads();
#pragma unroll
        for (int k = 0; k < 32; ++k) {
            float4 w0 = *(const float4*)&Ws[k * 132 + tx * 8];
            float4 w1 = *(const float4*)&Ws[k * 132 + tx * 8 + 4];
#pragma unroll
            for (int i = 0; i < 4; ++i) {
                float x = Xs[(ty * 4 + i) * 36 + k];
                acc[i][0] += x * w0.x; acc[i][1] += x * w0.y;
                acc[i][2] += x * w0.z; acc[i][3] += x * w0.w;
                acc[i][4] += x * w1.x; acc[i][5] += x * w1.y;
                acc[i][6] += x * w1.z; acc[i][7] += x * w1.w;
            }
        }
    }
#pragma unroll
    for (int i = 0; i < 4; ++i) {
        float* dst = g_gpart + ((size_t)(sel * 8 + kp) * 64 + ty * 4 + i) * 3072
                   + nt + tx * 8;
#pragma unroll
        for (int j = 0; j < 8; ++j) dst[j] = acc[i][j];
    }
}

// ---------------------------------------------------------------------------
// GRU gating
// ---------------------------------------------------------------------------
__global__ void k_gru_gate(const float* __restrict__ hst,
                           const float* __restrict__ b_ih,
                           const float* __restrict__ b_hh,
                           float* __restrict__ out)
{
    int idx = blockIdx.x * 256 + threadIdx.x;
    int b = idx >> 10, j = idx & 1023;
    float gi_r = 0.f, gi_z = 0.f, gi_n = 0.f;
    float gh_r = 0.f, gh_z = 0.f, gh_n = 0.f;
#pragma unroll
    for (int kp = 0; kp < 8; ++kp) {
        const float* pi = g_gpart + ((size_t)kp * 64 + b) * 3072;
        const float* ph = g_gpart + ((size_t)(8 + kp) * 64 + b) * 3072;
        gi_r += pi[j]; gi_z += pi[j + 1024]; gi_n += pi[j + 2048];
        gh_r += ph[j]; gh_z += ph[j + 1024]; gh_n += ph[j + 2048];
    }
    gi_r += b_ih[j]; gi_z += b_ih[j + 1024]; gi_n += b_ih[j + 2048];
    gh_r += b_hh[j]; gh_z += b_hh[j + 1024]; gh_n += b_hh[j + 2048];
    float r = sigmoidf_(gi_r + gh_r);
    float z = sigmoidf_(gi_z + gh_z);
    float n = tanhf(gi_n + r * gh_n);
    out[idx] = (1.f - z) * n + z * hst[idx];
}

// ---------------------------------------------------------------------------
// processed_query, split-K=32 batch-tiled: partial[kp][b][a]
// grid (4 ntiles of 128, 32 kp), block 256
// ---------------------------------------------------------------------------
__global__ __launch_bounds__(256) void k_pq_g(
    const float* __restrict__ rnn, const float* __restrict__ q_w)
{
    __shared__ float Xs[64 * 36];
    __shared__ float Ws[32 * 132];

    int tid = threadIdx.x;
    int nt = blockIdx.x * 128;
    int kb = blockIdx.y * 32;

    int ty = tid >> 4, tx = tid & 15;
    int r0 = tid >> 3, c8 = tid & 7;

    float acc[4][8];
#pragma unroll
    for (int i = 0; i < 4; ++i)
#pragma unroll
        for (int j = 0; j < 8; ++j) acc[i][j] = 0.f;

#pragma unroll
    for (int p = 0; p < 2; ++p) {
        int row = r0 + p * 32;
        *(float4*)&Xs[row * 36 + c8 * 4] = *(const float4*)(rnn + row * 1024 + kb + c8 * 4);
    }
#pragma unroll
    for (int p = 0; p < 4; ++p) {
        int j = r0 + p * 32;
        float4 w = *(const float4*)&q_w[(size_t)(nt + j) * 1024 + kb + c8 * 4];
        Ws[(c8 * 4 + 0) * 132 + j] = w.x;
        Ws[(c8 * 4 + 1) * 132 + j] = w.y;
        Ws[(c8 * 4 + 2) * 132 + j] = w.z;
        Ws[(c8 * 4 + 3) * 132 + j] = w.w;
    }
    __syncthreads();
#pragma unroll
    for (int k = 0; k < 32; ++k) {
        float4 w0 = *(const float4*)&Ws[k * 132 + tx * 8];
        float4 w1 = *(const float4*)&Ws[k * 132 + tx * 8 + 4];
#pragma unroll
        for (int i = 0; i < 4; ++i) {
            float x = Xs[(ty * 4 + i) * 36 + k];
            acc[i][0] += x * w0.x; acc[i][1] += x * w0.y;
            acc[i][2] += x * w0.z; acc[i][3] += x * w0.w;
            acc[i][4] += x * w1.x; acc[i][5] += x * w1.y;
            acc[i][6] += x * w1.z; acc[i][7] += x * w1.w;
        }
    }
#pragma unroll
    for (int i = 0; i < 4; ++i) {
        float* dst = g_pqpart + ((size_t)blockIdx.y * 64 + ty * 4 + i) * 512
                   + nt + tx * 8;
#pragma unroll
        for (int j = 0; j < 8; ++j) dst[j] = acc[i][j];
    }
}

__global__ void k_pq_comb(const float* __restrict__ q_b)
{
    int idx = blockIdx.x * 256 + threadIdx.x;  // 32768
    int a = idx & 511;
    float s = q_b[a];
#pragma unroll
    for (int kp = 0; kp < 32; ++kp) s += g_pqpart[kp * 32768 + idx];
    g_pq[idx] = s;
}

// ---------------------------------------------------------------------------
// location conv -> g_lconvh[b][t][f] (half)
// ---------------------------------------------------------------------------
__global__ __launch_bounds__(256) void k_conv(
    const float* __restrict__ atten, const float* __restrict__ conv_w)
{
    __shared__ float sA[2 * 1056];
    __shared__ float sW[16 * 62];
    int b = blockIdx.x, fg = blockIdx.y;
    int tid = threadIdx.x;
    for (int i = tid; i < 2 * 1056; i += 256) {
        int c = i / 1056;
        int p = i % 1056;
        int t = p - 15;
        float v = 0.f;
        if (t >= 0 && t < 1024) v = atten[b * 2048 + c * 1024 + t];
        sA[i] = v;
    }
    for (int i = tid; i < 16 * 62; i += 256) {
        int fo = i / 62, r = i % 62;
        sW[i] = conv_w[(fg * 16 + fo) * 62 + r];
    }
    __syncthreads();
#pragma unroll
    for (int p = 0; p < 4; ++p) {
        int t = tid + p * 256;
        float acc[16];
#pragma unroll
        for (int f = 0; f < 16; ++f) acc[f] = 0.f;
#pragma unroll
        for (int c = 0; c < 2; ++c)
#pragma unroll
            for (int k = 0; k < 31; ++k) {
                float a = sA[c * 1056 + t + k];
#pragma unroll
                for (int f = 0; f < 16; ++f) acc[f] += a * sW[f * 62 + c * 31 + k];
            }
        __half* dst = g_lconvh + (size_t)b * 32768 + t * 32 + fg * 16;
        uint4 o0, o1;
        o0.x = pack_h2(acc[0], acc[1]);   o0.y = pack_h2(acc[2], acc[3]);
        o0.z = pack_h2(acc[4], acc[5]);   o0.w = pack_h2(acc[6], acc[7]);
        o1.x = pack_h2(acc[8], acc[9]);   o1.y = pack_h2(acc[10], acc[11]);
        o1.z = pack_h2(acc[12], acc[13]); o1.w = pack_h2(acc[14], acc[15]);
        *reinterpret_cast<uint4*>(dst) = o0;
        *reinterpret_cast<uint4*>(dst + 8) = o1;
    }
}

// ---------------------------------------------------------------------------
// Energy GEMM, f16 mma.sync m16n8k16 + cp.async double-buffered pipeline.
// Block tile 128t x 128a, 8 warps (4x2). K = 8 chunks of 64 (annot) + 1 of 32 (conv).
// grid (4, 512), block 256, dynamic smem.
// ---------------------------------------------------------------------------
#define EPADH 72                       // halves per smem row (144B, conflict-free)
#define ETILEH (128 * EPADH)           // halves per tile
#define E_SMEM_BYTES (4 * ETILEH * 2 + 1024)

__global__ __launch_bounds__(256) void k_energy(
    const float* __restrict__ a_b, const float* __restrict__ loc_b,
    const float* __restrict__ v_w)
{
    extern __shared__ char smem[];
    __half* Ah[2] = { (__half*)smem,                    (__half*)(smem + 2 * ETILEH * 2) };
    __half* Bh[2] = { (__half*)(smem + ETILEH * 2),     (__half*)(smem + 3 * ETILEH * 2) };
    float* c_s = (float*)(smem + 4 * ETILEH * 2);
    float* v_s = c_s + 128;

    int tid = threadIdx.x;
    int warp = tid >> 5, lane = tid & 31;
    int wm = warp >> 1, wn = warp & 1;
    int g = lane >> 2, tg = lane & 3;

    int atile = blockIdx.x;
    int mtile = blockIdx.y;
    int b = mtile >> 3;
    int t0 = (mtile & 7) << 7;
    int abase = atile << 7;

    if (tid < 128) {
        int a = abase + tid;
        c_s[tid] = g_pq[b * 512 + a] + a_b[a] + loc_b[a];
        v_s[tid] = v_w[a];
    }

    const __half* baseA = g_annots_h + ((size_t)(b * 1024 + t0)) * 512;
    const __half* baseB = g_awh + (size_t)abase * 512;
    const __half* convA = g_lconvh + (size_t)b * 32768 + (size_t)t0 * 32;
    const __half* convB = g_locwh + (size_t)abase * 32;

    auto issue = [&](int kc, int bf) {
        if (kc < 8) {
            const __half* gA = baseA + kc * 64;
            const __half* gB = baseB + kc * 64;
#pragma unroll
            for (int p = 0; p < 4; ++p) {
                int lin = tid + p * 256;
                int row = lin >> 3, seg = lin & 7;
                cp_async16(&Ah[bf][row * EPADH + seg * 8], gA + (size_t)row * 512 + seg * 8);
            }
#pragma unroll
            for (int p = 0; p < 4; ++p) {
                int lin = tid + p * 256;
                int row = lin >> 3, seg = lin & 7;
                cp_async16(&Bh[bf][row * EPADH + seg * 8], gB + (size_t)row * 512 + seg * 8);
            }
        } else {
#pragma unroll
            for (int p = 0; p < 2; ++p) {
                int lin = tid + p * 256;
                int row = lin >> 2, seg = lin & 3;
                cp_async16(&Ah[bf][row * EPADH + seg * 8], convA + (size_t)row * 32 + seg * 8);
            }
#pragma unroll
            for (int p = 0; p < 2; ++p) {
                int lin = tid + p * 256;
                int row = lin >> 2, seg = lin & 3;
                cp_async16(&Bh[bf][row * EPADH + seg * 8], convB + (size_t)row * 32 + seg * 8);
            }
        }
        cp_commit();
    };

    float acc[2][8][4];
#pragma unroll
    for (int mf = 0; mf < 2; ++mf)
#pragma unroll
        for (int nf = 0; nf < 8; ++nf)
#pragma unroll
            for (int q = 0; q < 4; ++q) acc[mf][nf][q] = 0.f;

    issue(0, 0);

    for (int kc = 0; kc < 9; ++kc) {
        int bf = kc & 1;
        if (kc + 1 < 9) {
            issue(kc + 1, bf ^ 1);
            cp_wait<1>();
        } else {
            cp_wait<0>();
        }
        __syncthreads();

        const __half* AA = Ah[bf];
        const __half* BB = Bh[bf];
        int nks = (kc < 8) ? 4 : 2;
#pragma unroll
        for (int ks = 0; ks < 4; ++ks) {
            if (ks >= nks) break;
            int k0 = ks * 16;
            unsigned a_frag[2][4];
#pragma unroll
            for (int mf = 0; mf < 2; ++mf) {
                int rb = wm * 32 + mf * 16;
                a_frag[mf][0] = *(const unsigned*)(AA + (rb + g) * EPADH + k0 + 2 * tg);
                a_frag[mf][1] = *(const unsigned*)(AA + (rb + g + 8) * EPADH + k0 + 2 * tg);
                a_frag[mf][2] = *(const unsigned*)(AA + (rb + g) * EPADH + k0 + 8 + 2 * tg);
                a_frag[mf][3] = *(const unsigned*)(AA + (rb + g + 8) * EPADH + k0 + 8 + 2 * tg);
            }
#pragma unroll
            for (int nf = 0; nf < 8; ++nf) {
                int ar = wn * 64 + nf * 8 + g;
                unsigned b0 = *(const unsigned*)(BB + ar * EPADH + k0 + 2 * tg);
                unsigned b1 = *(const unsigned*)(BB + ar * EPADH + k0 + 8 + 2 * tg);
                mma_f16(acc[0][nf], a_frag[0], b0, b1);
                mma_f16(acc[1][nf], a_frag[1], b0, b1);
            }
        }
        __syncthreads();
    }

    // epilogue: bias + tanh + v-weight, reduce over a within warp
#pragma unroll
    for (int mf = 0; mf < 2; ++mf) {
#pragma unroll
        for (int rh = 0; rh < 2; ++rh) {
            float s = 0.f;
#pragma unroll
            for (int nf = 0; nf < 8; ++nf) {
                int a0 = wn * 64 + nf * 8 + 2 * tg;
                float x = acc[mf][nf][rh * 2 + 0] + c_s[a0];
                float y = acc[mf][nf][rh * 2 + 1] + c_s[a0 + 1];
                s += v_s[a0] * tanh_fast(x) + v_s[a0 + 1] * tanh_fast(y);
            }
            s += __shfl_xor_sync(0xffffffffu, s, 1);
            s += __shfl_xor_sync(0xffffffffu, s, 2);
            if (tg == 0) {
                int t = t0 + wm * 32 + mf * 16 + rh * 8 + g;
                g_part[((size_t)(atile * 2 + wn) * 64 + b) * 1024 + t] = s;
            }
        }
    }
}

// ---------------------------------------------------------------------------
// mask + sigmoid + row normalize -> alignment
// ---------------------------------------------------------------------------
__global__ void k_norm(const int* __restrict__ mask, float* __restrict__ out)
{
    int b = blockIdx.x, tid = threadIdx.x;
    __shared__ float red[256];
    float s[4];
    float loc = 0.f;
#pragma unroll
    for (int i = 0; i < 4; ++i) {
        int t = tid + i * 256;
        float raw = 0.f;
#pragma unroll
        for (int sl = 0; sl < 8; ++sl) raw += g_part[sl * 65536 + b * 1024 + t];
        float v = (mask[b * 1024 + t] != 0) ? 1.f / (1.f + expf(-raw)) : 0.f;
        s[i] = v;
        loc += v;
    }
    red[tid] = loc;
    __syncthreads();
    for (int st = 128; st; st >>= 1) {
        if (tid < st) red[tid] += red[tid + st];
        __syncthreads();
    }
    float inv = 1.f / red[0];
#pragma unroll
    for (int i = 0; i < 4; ++i)
        out[98304 + b * 1024 + tid + i * 256] = s[i] * inv;
}

// ---------------------------------------------------------------------------
// new_context[b,d] = sum_t align[b,t] * annots[b,t,d]
// ---------------------------------------------------------------------------
__global__ __launch_bounds__(512) void k_ctx(
    const float* __restrict__ annots, const float* __restrict__ align,
    float* __restrict__ outc)
{
    __shared__ float w[1024];
    __shared__ float red[512];
    int b = blockIdx.y, d0 = blockIdx.x * 128;
    int tid = threadIdx.x;
    for (int i = tid; i < 1024; i += 512) w[i] = align[b * 1024 + i];
    __syncthreads();
    int d = d0 + (tid & 127);
    int part = tid >> 7;
    const float* A = annots + (size_t)(b * 1024 + part * 256) * 512 + d;
    float acc = 0.f;
#pragma unroll 8
    for (int t = 0; t < 256; ++t) acc += w[part * 256 + t] * A[(size_t)t * 512];
    red[tid] = acc;
    __syncthreads();
    if (part == 0)
        outc[b * 512 + d] = red[tid] + red[tid + 128] + red[tid + 256] + red[tid + 384];
}

// ---------------------------------------------------------------------------
extern "C" void kernel_launch(void* const* d_in, const int* in_sizes, int n_in,
                              void* d_out, int out_size)
{
    const float* memory    = (const float*)d_in[0];
    const float* context   = (const float*)d_in[1];
    const float* rnn_state = (const float*)d_in[2];
    const float* annots    = (const float*)d_in[3];
    const float* atten     = (const float*)d_in[4];
    const int*   mask      = (const int*)d_in[5];

    int w = 6;
    if (n_in >= 19 && in_sizes[6] == 1) w = 7;

    const float* W_ih   = (const float*)d_in[w + 0];
    const float* W_hh   = (const float*)d_in[w + 1];
    const float* b_ih   = (const float*)d_in[w + 2];
    const float* b_hh   = (const float*)d_in[w + 3];
    const float* conv_w = (const float*)d_in[w + 4];
    const float* loc_w  = (const float*)d_in[w + 5];
    const float* loc_b  = (const float*)d_in[w + 6];
    const float* q_w    = (const float*)d_in[w + 7];
    const float* q_b    = (const float*)d_in[w + 8];
    const float* a_w    = (const float*)d_in[w + 9];
    const float* a_b    = (const float*)d_in[w + 10];
    const float* v_w    = (const float*)d_in[w + 11];

    float* out = (float*)d_out;
    // layout: [rnn_output 64*1024][new_context 64*512][alignment 64*1024]

    static int smem_set = 0;
    if (!smem_set) {
        cudaFuncSetAttribute(k_energy, cudaFuncAttributeMaxDynamicSharedMemorySize,
                             E_SMEM_BYTES);
        smem_set = 1;
    }

    k_cvt_annots<<<16384, 256>>>(annots);
    k_cvt_w<<<136, 256>>>(a_w, loc_w);
    k_gru_gemm<<<dim3(24, 8, 2), 256>>>(memory, context, rnn_state, W_ih, W_hh);
    k_conv<<<dim3(64, 2), 256>>>(atten, conv_w);
    k_gru_gate<<<256, 256>>>(rnn_state, b_ih, b_hh, out);
    k_pq_g<<<dim3(4, 32), 256>>>(out, q_w);
    k_pq_comb<<<128, 256>>>(q_b);
    k_energy<<<dim3(4, 512), 256, E_SMEM_BYTES>>>(a_b, loc_b, v_w);
    k_norm<<<64, 256>>>(mask, out);
    k_ctx<<<dim3(4, 64), 512>>>(annots, out + 98304, out + 65536);
}